// round 3
// baseline (speedup 1.0000x reference)
#include <cuda_runtime.h>
#include <stdint.h>

// preds: [32, 3, 640, 640] fp32
#define B_    32
#define H_    640
#define W_    640
#define HW_   (H_ * W_)          // 409600
#define TOPK_ 1000
#define NBUCK 4096
#define CAP   4096               // candidate cap per image
#define TG    2.6f               // static fast-path threshold (p~0.0047 -> ~1900/img)

// Scratch (device globals; zero-initialized at module load; k_select restores
// g_count to 0 at the end of every execution so graph replays are deterministic)
__device__ unsigned long long g_cand[B_ * CAP];
__device__ int                g_count[B_];

// Order-preserving bijection float -> uint (monotone increasing)
__device__ __forceinline__ unsigned int ordf(float x) {
    unsigned int u = __float_as_uint(x);
    return (u & 0x80000000u) ? ~u : (u | 0x80000000u);
}

// ---------------------------------------------------------------------------
// Kernel 1: single streaming pass — compact all scores >= TG into 64-bit keys
//   key = (ordered_score << 32) | (0xFFFFFFFF - idx)
// Descending key order == (score desc, index asc) == jax.lax.top_k order.
// grid (25, 32) x 512 threads; each thread: 8 independent float4 loads.
// ---------------------------------------------------------------------------
__global__ void k_pass1(const float* __restrict__ preds) {
    const int b = blockIdx.y;
    const float4* sc = (const float4*)(preds + (size_t)b * 3 * HW_);
    const int tid = blockIdx.x * 512 + threadIdx.x;   // 0..12799

    float4 v[8];
#pragma unroll
    for (int j = 0; j < 8; j++) v[j] = sc[tid + j * 12800];

#pragma unroll
    for (int j = 0; j < 8; j++) {
        const int i4 = tid + j * 12800;
        const float f[4] = {v[j].x, v[j].y, v[j].z, v[j].w};
#pragma unroll
        for (int k = 0; k < 4; k++) {
            if (f[k] >= TG) {
                const int pos = atomicAdd(&g_count[b], 1);
                if (pos < CAP) {
                    const unsigned int o = ordf(f[k]);
                    const unsigned int idx = (unsigned int)(i4 * 4 + k);
                    g_cand[b * CAP + pos] =
                        ((unsigned long long)o << 32) | (unsigned long long)(0xFFFFFFFFu - idx);
                }
            }
        }
    }
}

// ---------------------------------------------------------------------------
// Kernel 2: one block (1024 thr) per image.
//   a) if the fast-path candidate count is invalid (<TOPK or >CAP), inline
//      fallback: exact 12-bit radix bucket threshold over the full score
//      channel, recompact into g_cand. (Never taken for N(0,1) data; costs
//      one branch.)
//   b) load candidate keys into shared, exact rank via all-pairs compare
//      (keys unique -> ranks are a permutation), emit boxes/scores/keep.
//   c) reset g_count for the next graph replay.
// ---------------------------------------------------------------------------
__global__ void k_select(const float* __restrict__ preds, float* __restrict__ out) {
    __shared__ __align__(16) unsigned char buf[CAP * 8];  // 32 KB, phase-aliased
    __shared__ int s_T, s_cnt;

    const int b = blockIdx.x;
    const int t = threadIdx.x;

    int M = g_count[b];

    // ---------------- fallback (early-exit branch) ----------------
    if (M < TOPK_ || M > CAP) {
        unsigned int* hist = (unsigned int*)buf;                 // 16 KB
        unsigned int* part = (unsigned int*)(buf + 16384);       //  4 KB

        for (int i = t; i < NBUCK; i += 1024) hist[i] = 0u;
        if (t == 0) { s_T = 0; s_cnt = 0; }
        __syncthreads();

        const float4* sc = (const float4*)(preds + (size_t)b * 3 * HW_);
        for (int i = t; i < HW_ / 4; i += 1024) {
            const float4 v = sc[i];
            atomicAdd(&hist[ordf(v.x) >> 20], 1u);
            atomicAdd(&hist[ordf(v.y) >> 20], 1u);
            atomicAdd(&hist[ordf(v.z) >> 20], 1u);
            atomicAdd(&hist[ordf(v.w) >> 20], 1u);
        }
        __syncthreads();

        // inclusive suffix scan over 4096 buckets (4 per thread)
        const unsigned int p = hist[4 * t] + hist[4 * t + 1] + hist[4 * t + 2] + hist[4 * t + 3];
        part[t] = p;
        __syncthreads();
        for (int off = 1; off < 1024; off <<= 1) {
            unsigned int v = 0;
            if (t + off < 1024) v = part[t + off];
            __syncthreads();
            part[t] += v;
            __syncthreads();
        }
        unsigned int acc = part[t] - p;
        for (int j = 3; j >= 0; j--) {
            acc += hist[4 * t + j];
            if (acc >= (unsigned)TOPK_) { atomicMax(&s_T, 4 * t + j); break; }
        }
        __syncthreads();
        const unsigned int T = (unsigned int)s_T;

        for (int i = t; i < HW_ / 4; i += 1024) {
            const float4 v = sc[i];
            const float f[4] = {v.x, v.y, v.z, v.w};
#pragma unroll
            for (int k = 0; k < 4; k++) {
                const unsigned int o = ordf(f[k]);
                if ((o >> 20) >= T) {
                    const int pos = atomicAdd(&s_cnt, 1);
                    if (pos < CAP) {
                        const unsigned int idx = (unsigned int)(i * 4 + k);
                        g_cand[b * CAP + pos] =
                            ((unsigned long long)o << 32) | (unsigned long long)(0xFFFFFFFFu - idx);
                    }
                }
            }
        }
        __syncthreads();
        M = min(s_cnt, CAP);
        __syncthreads();  // buf reuse barrier
    }
    M = min(M, CAP);

    // ---------------- exact rank + emit ----------------
    unsigned long long* keys = (unsigned long long*)buf;         // 32 KB
    for (int i = t; i < M; i += 1024) keys[i] = g_cand[b * CAP + i];
    __syncthreads();

    const float* ph = preds + (size_t)b * 3 * HW_ + HW_;
    const float* pw = ph + HW_;
    float* boxes  = out;                              // [B, K, 4]
    float* scores = out + (size_t)B_ * TOPK_ * 4;     // [B, K]
    float* keep   = scores + (size_t)B_ * TOPK_;      // [B, K]

    for (int c = t; c < M; c += 1024) {
        const unsigned long long k = keys[c];
        int rank = 0;
#pragma unroll 8
        for (int j = 0; j < M; j++) rank += (keys[j] > k);
        if (rank < TOPK_) {
            const unsigned int o = (unsigned int)(k >> 32);
            const unsigned int u = (o & 0x80000000u) ? (o ^ 0x80000000u) : ~o;
            const float score = __uint_as_float(u);
            const unsigned int idx = 0xFFFFFFFFu - (unsigned int)(k & 0xFFFFFFFFull);

            const float h = fmaxf(ph[idx], 1e-6f) * (float)H_;
            const float w = fmaxf(pw[idx], 1e-6f) * (float)W_;
            const float cx = (float)(idx % W_);
            const float cy = (float)(idx / W_);

            float* bx = boxes + ((size_t)b * TOPK_ + rank) * 4;
            bx[0] = cx - 0.5f * w;
            bx[1] = cy - 0.5f * h;
            bx[2] = cx + 0.5f * w;
            bx[3] = cy + 0.5f * h;
            scores[b * TOPK_ + rank] = score;
            keep[b * TOPK_ + rank]   = 1.0f;
        }
    }

    // reset state for next graph replay
    if (t == 0) g_count[b] = 0;
}

// ---------------------------------------------------------------------------
extern "C" void kernel_launch(void* const* d_in, const int* in_sizes, int n_in,
                              void* d_out, int out_size) {
    const float* preds = (const float*)d_in[0];
    float* out = (float*)d_out;

    dim3 gp(25, B_);
    k_pass1<<<gp, 512>>>(preds);
    k_select<<<B_, 1024>>>(preds, out);
}

// round 4
// speedup vs baseline: 1.9518x; 1.9518x over previous
#include <cuda_runtime.h>
#include <stdint.h>

// preds: [32, 3, 640, 640] fp32
#define B_    32
#define H_    640
#define W_    640
#define HW_   (H_ * W_)          // 409600
#define TOPK_ 1000
#define NBUCK 4096
#define CAP   4096               // candidate cap per image
#define TG    2.6f               // static fast-path threshold (p~0.0047 -> ~1900/img)

typedef unsigned long long ull;

// Scratch (device globals; zero at module load; k_sort restores g_count to 0
// at the end of every execution so graph replays are deterministic)
__device__ ull g_cand[B_ * CAP];
__device__ int g_count[B_];

// Order-preserving bijection float -> uint (monotone increasing)
__device__ __forceinline__ unsigned int ordf(float x) {
    unsigned int u = __float_as_uint(x);
    return (u & 0x80000000u) ? ~u : (u | 0x80000000u);
}

// ---------------------------------------------------------------------------
// Kernel 1: single streaming pass over the score channel.
// grid (25, 32) x 512 threads; 8 float4 per thread, front-batched loads.
// Hits (score >= TG) collected via per-thread 32-bit mask -> ONE atomicAdd
// per hitting thread (~14% of threads), then predicated emits.
//   key = (ordered_score << 32) | (0xFFFFFFFF - idx)
// Descending key order == (score desc, index asc) == jax.lax.top_k order.
// ---------------------------------------------------------------------------
__global__ void __launch_bounds__(512, 2) k_pass1(const float* __restrict__ preds) {
    const int b = blockIdx.y;
    const float4* __restrict__ sc = (const float4*)(preds + (size_t)b * 3 * HW_);
    const int tid = blockIdx.x * 512 + threadIdx.x;   // 0..12799

    float4 v[8];
#pragma unroll
    for (int j = 0; j < 8; j++) v[j] = sc[tid + j * 12800];

    unsigned int m = 0;
#pragma unroll
    for (int j = 0; j < 8; j++) {
        m |= (v[j].x >= TG) ? (1u << (4 * j + 0)) : 0u;
        m |= (v[j].y >= TG) ? (1u << (4 * j + 1)) : 0u;
        m |= (v[j].z >= TG) ? (1u << (4 * j + 2)) : 0u;
        m |= (v[j].w >= TG) ? (1u << (4 * j + 3)) : 0u;
    }

    if (m) {
        int base = atomicAdd(&g_count[b], __popc(m));
        int off = 0;
#pragma unroll
        for (int j = 0; j < 8; j++) {
            const int i4 = tid + j * 12800;
            const float f[4] = {v[j].x, v[j].y, v[j].z, v[j].w};
#pragma unroll
            for (int k = 0; k < 4; k++) {
                if (m & (1u << (4 * j + k))) {
                    const int pos = base + off;
                    if (pos < CAP) {
                        const unsigned int o = ordf(f[k]);
                        const unsigned int idx = (unsigned int)(i4 * 4 + k);
                        g_cand[b * CAP + pos] =
                            ((ull)o << 32) | (ull)(0xFFFFFFFFu - idx);
                    }
                    off++;
                }
            }
        }
    }
}

// ---------------------------------------------------------------------------
// Kernel 2: one block (1024 thr) per image.
//   a) never-taken fallback: exact 12-bit radix threshold over the full score
//      channel if the fast-path count is invalid (<TOPK or >CAP).
//   b) bitonic sort (descending) of candidate keys in shared (n = 2048 or
//      4096, padded with key 0 which is strictly below every real key since
//      real low words are 0xFFFFFFFF - idx >= 0xFFF9C000).
//   c) threads 0..999 emit boxes/scores/keep at rank = sorted position.
//   d) reset g_count for next graph replay.
// ---------------------------------------------------------------------------
__global__ void k_sort(const float* __restrict__ preds, float* __restrict__ out) {
    __shared__ __align__(16) unsigned char buf[CAP * 8];  // 32 KB, phase-aliased
    __shared__ int s_T, s_cnt;

    const int b = blockIdx.x;
    const int t = threadIdx.x;

    int M = g_count[b];

    // ---------------- fallback (never taken for valid fast path) ----------------
    if (M < TOPK_ || M > CAP) {
        unsigned int* hist = (unsigned int*)buf;               // 16 KB
        unsigned int* part = (unsigned int*)(buf + 16384);     //  4 KB

        for (int i = t; i < NBUCK; i += 1024) hist[i] = 0u;
        if (t == 0) { s_T = 0; s_cnt = 0; }
        __syncthreads();

        const float4* sc = (const float4*)(preds + (size_t)b * 3 * HW_);
        for (int i = t; i < HW_ / 4; i += 1024) {
            const float4 v = sc[i];
            atomicAdd(&hist[ordf(v.x) >> 20], 1u);
            atomicAdd(&hist[ordf(v.y) >> 20], 1u);
            atomicAdd(&hist[ordf(v.z) >> 20], 1u);
            atomicAdd(&hist[ordf(v.w) >> 20], 1u);
        }
        __syncthreads();

        const unsigned int p = hist[4 * t] + hist[4 * t + 1] + hist[4 * t + 2] + hist[4 * t + 3];
        part[t] = p;
        __syncthreads();
        for (int off = 1; off < 1024; off <<= 1) {
            unsigned int vv = 0;
            if (t + off < 1024) vv = part[t + off];
            __syncthreads();
            part[t] += vv;
            __syncthreads();
        }
        unsigned int acc = part[t] - p;
        for (int j = 3; j >= 0; j--) {
            acc += hist[4 * t + j];
            if (acc >= (unsigned)TOPK_) { atomicMax(&s_T, 4 * t + j); break; }
        }
        __syncthreads();
        const unsigned int T = (unsigned int)s_T;

        for (int i = t; i < HW_ / 4; i += 1024) {
            const float4 v = sc[i];
            const float f[4] = {v.x, v.y, v.z, v.w};
#pragma unroll
            for (int k = 0; k < 4; k++) {
                const unsigned int o = ordf(f[k]);
                if ((o >> 20) >= T) {
                    const int pos = atomicAdd(&s_cnt, 1);
                    if (pos < CAP) {
                        const unsigned int idx = (unsigned int)(i * 4 + k);
                        g_cand[b * CAP + pos] =
                            ((ull)o << 32) | (ull)(0xFFFFFFFFu - idx);
                    }
                }
            }
        }
        __syncthreads();
        M = min(s_cnt, CAP);
        __syncthreads();  // buf reuse barrier
    }
    M = min(M, CAP);

    // ---------------- bitonic sort (descending) ----------------
    ull* keys = (ull*)buf;                                     // up to 32 KB
    const int n = (M <= 2048) ? 2048 : 4096;
    for (int i = t; i < n; i += 1024) keys[i] = (i < M) ? g_cand[b * CAP + i] : 0ull;
    __syncthreads();

    for (int k = 2; k <= n; k <<= 1) {
        for (int j = k >> 1; j > 0; j >>= 1) {
            for (int i = t; i < n; i += 1024) {
                const int ixj = i ^ j;
                if (ixj > i) {
                    const ull a = keys[i];
                    const ull c = keys[ixj];
                    const bool up = ((i & k) == 0);
                    if (up ? (a < c) : (a > c)) { keys[i] = c; keys[ixj] = a; }
                }
            }
            __syncthreads();
        }
    }

    // ---------------- emit ----------------
    const float* ph = preds + (size_t)b * 3 * HW_ + HW_;
    const float* pw = ph + HW_;
    float* boxes  = out;                              // [B, K, 4]
    float* scores = out + (size_t)B_ * TOPK_ * 4;     // [B, K]
    float* keep   = scores + (size_t)B_ * TOPK_;      // [B, K]

    if (t < TOPK_) {
        const ull kk = keys[t];
        const unsigned int o = (unsigned int)(kk >> 32);
        const unsigned int u = (o & 0x80000000u) ? (o ^ 0x80000000u) : ~o;
        const float score = __uint_as_float(u);
        const unsigned int idx = 0xFFFFFFFFu - (unsigned int)(kk & 0xFFFFFFFFull);

        const float h = fmaxf(ph[idx], 1e-6f) * (float)H_;
        const float w = fmaxf(pw[idx], 1e-6f) * (float)W_;
        const float cx = (float)(idx % W_);
        const float cy = (float)(idx / W_);

        float* bx = boxes + ((size_t)b * TOPK_ + t) * 4;
        bx[0] = cx - 0.5f * w;
        bx[1] = cy - 0.5f * h;
        bx[2] = cx + 0.5f * w;
        bx[3] = cy + 0.5f * h;
        scores[b * TOPK_ + t] = score;
        keep[b * TOPK_ + t]   = 1.0f;
    }

    // reset state for next graph replay
    if (t == 0) g_count[b] = 0;
}

// ---------------------------------------------------------------------------
extern "C" void kernel_launch(void* const* d_in, const int* in_sizes, int n_in,
                              void* d_out, int out_size) {
    const float* preds = (const float*)d_in[0];
    float* out = (float*)d_out;

    dim3 gp(25, B_);
    k_pass1<<<gp, 512>>>(preds);
    k_sort<<<B_, 1024>>>(preds, out);
}

// round 5
// speedup vs baseline: 2.4084x; 1.2340x over previous
#include <cuda_runtime.h>
#include <stdint.h>

// preds: [32, 3, 640, 640] fp32
#define B_    32
#define H_    640
#define W_    640
#define HW_   (H_ * W_)          // 409600
#define TOPK_ 1000
#define NBUCK 4096
#define CAP   4096
#define TG    2.6f               // static fast-path threshold (p~0.0047 -> ~1900/img)
#define BX    100                // blocks per image
#define TPB   256
#define VEC   4                  // float4 per thread (16 floats)

typedef unsigned long long ull;

// Device scratch (zero at load; kernel restores counters each execution)
__device__ ull g_cand[B_ * CAP];
__device__ ull g_sorted[B_ * CAP];
__device__ int g_count[B_];
__device__ int g_done[B_];

// Order-preserving bijection float -> uint (monotone increasing)
__device__ __forceinline__ unsigned int ordf(float x) {
    unsigned int u = __float_as_uint(x);
    return (u & 0x80000000u) ? ~u : (u | 0x80000000u);
}

__global__ void __launch_bounds__(TPB) k_fused(const float* __restrict__ preds,
                                               float* __restrict__ out) {
    __shared__ unsigned int sh_hist[NBUCK];    // 16 KB
    __shared__ unsigned int sh_start[NBUCK];   // 16 KB
    __shared__ unsigned int sh_part[TPB];
    __shared__ unsigned int sh_rmin[8], sh_rmax[8];
    __shared__ unsigned int sh_mn, sh_sh;
    __shared__ int sh_flag, sh_T, sh_c2;

    const int b = blockIdx.y;
    const int t = threadIdx.x;
    const int lane = t & 31;

    // ======================= PASS PHASE =======================
    {
        const float4* __restrict__ sc = (const float4*)(preds + (size_t)b * 3 * HW_);
        const int tid = blockIdx.x * TPB + t;            // 0..25599

        float4 v[VEC];
#pragma unroll
        for (int j = 0; j < VEC; j++) v[j] = __ldcs(&sc[tid + j * 25600]);

        unsigned int m = 0;
#pragma unroll
        for (int j = 0; j < VEC; j++) {
            m |= (v[j].x >= TG) ? (1u << (4 * j + 0)) : 0u;
            m |= (v[j].y >= TG) ? (1u << (4 * j + 1)) : 0u;
            m |= (v[j].z >= TG) ? (1u << (4 * j + 2)) : 0u;
            m |= (v[j].w >= TG) ? (1u << (4 * j + 3)) : 0u;
        }

        const int nh = __popc(m);
        // warp inclusive prefix sum of nh
        int pre = nh;
#pragma unroll
        for (int off = 1; off < 32; off <<= 1) {
            int x = __shfl_up_sync(0xFFFFFFFFu, pre, off);
            if (lane >= off) pre += x;
        }
        const int tot = __shfl_sync(0xFFFFFFFFu, pre, 31);
        if (tot) {
            int base = 0;
            if (lane == 31) base = atomicAdd(&g_count[b], tot);
            base = __shfl_sync(0xFFFFFFFFu, base, 31);
            int pos = base + pre - nh;
#pragma unroll
            for (int j = 0; j < VEC; j++) {
                const int i4 = tid + j * 25600;
                const float f0 = v[j].x, f1 = v[j].y, f2 = v[j].z, f3 = v[j].w;
#pragma unroll
                for (int k = 0; k < 4; k++) {
                    if (m & (1u << (4 * j + k))) {
                        if (pos < CAP) {
                            const float f = (k == 0) ? f0 : (k == 1) ? f1 : (k == 2) ? f2 : f3;
                            const unsigned int o = ordf(f);
                            const unsigned int idx = (unsigned int)(i4 * 4 + k);
                            g_cand[b * CAP + pos] =
                                ((ull)o << 32) | (ull)(0xFFFFFFFFu - idx);
                        }
                        pos++;
                    }
                }
            }
        }
    }

    // ============== DONE-COUNTER: last block per image selects ==============
    __threadfence();
    __syncthreads();
    if (t == 0) {
        const int old = atomicAdd(&g_done[b], 1);
        sh_flag = (old == BX - 1);
    }
    __syncthreads();
    if (!sh_flag) return;
    __threadfence();

    int M = g_count[b];

    // ================= FALLBACK (never taken for valid fast path) =================
    if (M < TOPK_ || M > CAP) {
        for (int i = t; i < NBUCK; i += TPB) sh_hist[i] = 0u;
        if (t == 0) { sh_T = 0; sh_c2 = 0; }
        __syncthreads();

        const float4* sc = (const float4*)(preds + (size_t)b * 3 * HW_);
        for (int i = t; i < HW_ / 4; i += TPB) {
            const float4 w = sc[i];
            atomicAdd(&sh_hist[ordf(w.x) >> 20], 1u);
            atomicAdd(&sh_hist[ordf(w.y) >> 20], 1u);
            atomicAdd(&sh_hist[ordf(w.z) >> 20], 1u);
            atomicAdd(&sh_hist[ordf(w.w) >> 20], 1u);
        }
        __syncthreads();

        unsigned int seg = 0;
        for (int j = 15; j >= 0; j--) seg += sh_hist[t * 16 + j];
        sh_part[t] = seg;
        __syncthreads();
        for (int off = 1; off < TPB; off <<= 1) {
            unsigned int vv = (t + off < TPB) ? sh_part[t + off] : 0u;
            __syncthreads();
            sh_part[t] += vv;
            __syncthreads();
        }
        unsigned int acc = sh_part[t] - seg;
        for (int j = 15; j >= 0; j--) {
            acc += sh_hist[t * 16 + j];
            if (acc >= (unsigned)TOPK_) { atomicMax(&sh_T, t * 16 + j); break; }
        }
        __syncthreads();
        const unsigned int T = (unsigned int)sh_T;

        for (int i = t; i < HW_ / 4; i += TPB) {
            const float4 w = sc[i];
            const float f[4] = {w.x, w.y, w.z, w.w};
#pragma unroll
            for (int k = 0; k < 4; k++) {
                const unsigned int o = ordf(f[k]);
                if ((o >> 20) >= T) {
                    const int p = atomicAdd(&sh_c2, 1);
                    if (p < CAP) {
                        const unsigned int idx = (unsigned int)(i * 4 + k);
                        g_cand[b * CAP + p] = ((ull)o << 32) | (ull)(0xFFFFFFFFu - idx);
                    }
                }
            }
        }
        __syncthreads();
        M = min(sh_c2, CAP);
    }
    M = min(M, CAP);

    // ================= COUNTING SORT (descending) =================
    // min/max of candidate high words
    unsigned int lmin = 0xFFFFFFFFu, lmax = 0u;
    for (int i = t; i < M; i += TPB) {
        const unsigned int h = (unsigned int)(g_cand[b * CAP + i] >> 32);
        lmin = min(lmin, h);
        lmax = max(lmax, h);
    }
#pragma unroll
    for (int off = 16; off > 0; off >>= 1) {
        lmin = min(lmin, __shfl_down_sync(0xFFFFFFFFu, lmin, off));
        lmax = max(lmax, __shfl_down_sync(0xFFFFFFFFu, lmax, off));
    }
    if (lane == 0) { sh_rmin[t >> 5] = lmin; sh_rmax[t >> 5] = lmax; }
    for (int i = t; i < NBUCK; i += TPB) sh_hist[i] = 0u;
    __syncthreads();
    if (t == 0) {
        unsigned int mn = 0xFFFFFFFFu, mx = 0u;
#pragma unroll
        for (int i = 0; i < 8; i++) { mn = min(mn, sh_rmin[i]); mx = max(mx, sh_rmax[i]); }
        const unsigned int range = mx - mn;
        const int bits = 32 - __clz(range | 1u);
        sh_sh = (bits > 12) ? (unsigned)(bits - 12) : 0u;
        sh_mn = mn;
    }
    __syncthreads();
    const unsigned int mn = sh_mn, shf = sh_sh;

    // histogram
    for (int i = t; i < M; i += TPB) {
        const unsigned int h = (unsigned int)(g_cand[b * CAP + i] >> 32);
        atomicAdd(&sh_hist[(h - mn) >> shf], 1u);
    }
    __syncthreads();

    // suffix scan: sh_start[bk] = #elements in buckets > bk (i.e. higher score)
    unsigned int seg = 0;
    for (int j = 15; j >= 0; j--) seg += sh_hist[t * 16 + j];
    sh_part[t] = seg;
    __syncthreads();
    for (int off = 1; off < TPB; off <<= 1) {
        unsigned int vv = (t + off < TPB) ? sh_part[t + off] : 0u;
        __syncthreads();
        sh_part[t] += vv;
        __syncthreads();
    }
    unsigned int run = sh_part[t] - seg;
    for (int j = 15; j >= 0; j--) {
        sh_start[t * 16 + j] = run;
        run += sh_hist[t * 16 + j];
    }
    __syncthreads();

    // reset hist -> intra-bucket counters
    for (int i = t; i < NBUCK; i += TPB) sh_hist[i] = 0u;
    __syncthreads();

    // scatter
    for (int i = t; i < M; i += TPB) {
        const ull key = g_cand[b * CAP + i];
        const unsigned int bk = ((unsigned int)(key >> 32) - mn) >> shf;
        const unsigned int p = sh_start[bk] + atomicAdd(&sh_hist[bk], 1u);
        g_sorted[b * CAP + p] = key;
    }
    __syncthreads();

    // per-bucket insertion sort (descending by full key) for buckets
    // intersecting [0, TOPK)
    for (int bk = t; bk < NBUCK; bk += TPB) {
        const unsigned int c = sh_hist[bk];
        if (c > 1u) {
            const unsigned int st = sh_start[bk];
            if (st < (unsigned)TOPK_) {
                ull* s2 = &g_sorted[b * CAP + st];
                for (unsigned int a = 1; a < c; a++) {
                    const ull kv = s2[a];
                    int p2 = (int)a - 1;
                    while (p2 >= 0 && s2[p2] < kv) { s2[p2 + 1] = s2[p2]; p2--; }
                    s2[p2 + 1] = kv;
                }
            }
        }
    }
    __syncthreads();

    // ================= EMIT =================
    const float* ph = preds + (size_t)b * 3 * HW_ + HW_;
    const float* pw = ph + HW_;
    float* boxes  = out;                              // [B, K, 4]
    float* scores = out + (size_t)B_ * TOPK_ * 4;     // [B, K]
    float* keep   = scores + (size_t)B_ * TOPK_;      // [B, K]

    for (int p = t; p < TOPK_; p += TPB) {
        const ull kk = g_sorted[b * CAP + p];
        const unsigned int o = (unsigned int)(kk >> 32);
        const unsigned int u = (o & 0x80000000u) ? (o ^ 0x80000000u) : ~o;
        const float score = __uint_as_float(u);
        const unsigned int idx = 0xFFFFFFFFu - (unsigned int)(kk & 0xFFFFFFFFull);

        const float h = fmaxf(ph[idx], 1e-6f) * (float)H_;
        const float w = fmaxf(pw[idx], 1e-6f) * (float)W_;
        const float cx = (float)(idx % W_);
        const float cy = (float)(idx / W_);

        float* bx = boxes + ((size_t)b * TOPK_ + p) * 4;
        bx[0] = cx - 0.5f * w;
        bx[1] = cy - 0.5f * h;
        bx[2] = cx + 0.5f * w;
        bx[3] = cy + 0.5f * h;
        scores[b * TOPK_ + p] = score;
        keep[b * TOPK_ + p]   = 1.0f;
    }

    // reset state for next graph replay
    if (t == 0) { g_count[b] = 0; g_done[b] = 0; }
}

// ---------------------------------------------------------------------------
extern "C" void kernel_launch(void* const* d_in, const int* in_sizes, int n_in,
                              void* d_out, int out_size) {
    const float* preds = (const float*)d_in[0];
    float* out = (float*)d_out;

    dim3 g(BX, B_);
    k_fused<<<g, TPB>>>(preds, out);
}

// round 6
// speedup vs baseline: 4.0087x; 1.6644x over previous
#include <cuda_runtime.h>
#include <stdint.h>

// preds: [32, 3, 640, 640] fp32
#define B_    32
#define H_    640
#define W_    640
#define HW_   (H_ * W_)          // 409600
#define TOPK_ 1000
#define NB2   2048               // tail sort buckets
#define CAP   4096
#define TG    2.6f               // static fast-path threshold (p~0.0047 -> ~1900/img)
#define BX    100                // blocks per image
#define TPB   256
#define STAGE 1024               // per-block staging slots

typedef unsigned long long ull;

// Device scratch (zero at load; kernel restores counters each execution)
__device__ ull g_cand[B_ * CAP];
__device__ ull g_sorted[B_ * CAP];
__device__ int g_count[B_];
__device__ int g_done[B_];

// Order-preserving bijection float -> uint (monotone increasing)
__device__ __forceinline__ unsigned int ordf(float x) {
    unsigned int u = __float_as_uint(x);
    return (u & 0x80000000u) ? ~u : (u | 0x80000000u);
}

__global__ void __launch_bounds__(TPB, 6) k_fused(const float* __restrict__ preds,
                                                  float* __restrict__ out) {
    // 16 KB aliased buffer: pass uses stage[1024] (8 KB);
    // tail uses hist[2048] + start[2048] (8 KB + 8 KB)
    __shared__ __align__(16) unsigned char buf[16384];
    __shared__ unsigned int sh_part[TPB];
    __shared__ unsigned int sh_rmin[8], sh_rmax[8];
    __shared__ unsigned int sh_mn, sh_sh;
    __shared__ int sh_cnt, sh_base, sh_ovf, sh_flag, sh_T, sh_c2;

    const int b = blockIdx.y;
    const int t = threadIdx.x;
    const int lane = t & 31;

    // ======================= PASS PHASE =======================
    {
        ull* stage = (ull*)buf;
        if (t == 0) { sh_cnt = 0; sh_ovf = 0; }
        __syncthreads();

        const float4* __restrict__ sc = (const float4*)(preds + (size_t)b * 3 * HW_);
        const int tid = blockIdx.x * TPB + t;            // 0..25599

        float4 v[4];
#pragma unroll
        for (int j = 0; j < 4; j++) v[j] = sc[tid + j * 25600];

        unsigned int m = 0;
#pragma unroll
        for (int j = 0; j < 4; j++) {
            m |= (v[j].x >= TG) ? (1u << (4 * j + 0)) : 0u;
            m |= (v[j].y >= TG) ? (1u << (4 * j + 1)) : 0u;
            m |= (v[j].z >= TG) ? (1u << (4 * j + 2)) : 0u;
            m |= (v[j].w >= TG) ? (1u << (4 * j + 3)) : 0u;
        }

        const int nh = __popc(m);
        if (__ballot_sync(0xFFFFFFFFu, nh) != 0) {
            // warp inclusive prefix of nh
            int pre = nh;
#pragma unroll
            for (int off = 1; off < 32; off <<= 1) {
                int x = __shfl_up_sync(0xFFFFFFFFu, pre, off);
                if (lane >= off) pre += x;
            }
            const int tot = __shfl_sync(0xFFFFFFFFu, pre, 31);
            int wbase = 0;
            if (lane == 31) wbase = atomicAdd(&sh_cnt, tot);   // shared atomic (cheap)
            wbase = __shfl_sync(0xFFFFFFFFu, wbase, 31);

            int pos = wbase + pre - nh;
            if (nh) {
#pragma unroll
                for (int j = 0; j < 4; j++) {
                    const int i4 = tid + j * 25600;
                    const float f0 = v[j].x, f1 = v[j].y, f2 = v[j].z, f3 = v[j].w;
#pragma unroll
                    for (int k = 0; k < 4; k++) {
                        if (m & (1u << (4 * j + k))) {
                            if (pos < STAGE) {
                                const float f = (k == 0) ? f0 : (k == 1) ? f1 : (k == 2) ? f2 : f3;
                                const unsigned int o = ordf(f);
                                const unsigned int idx = (unsigned int)(i4 * 4 + k);
                                stage[pos] = ((ull)o << 32) | (ull)(0xFFFFFFFFu - idx);
                            } else {
                                sh_ovf = 1;
                            }
                            pos++;
                        }
                    }
                }
            }
        }
        __syncthreads();

        // ONE global atomic per block; poison count on stage overflow
        if (t == 0) {
            int add = sh_cnt + (sh_ovf ? 1000000 : 0);
            sh_base = add ? atomicAdd(&g_count[b], add) : 0;
        }
        __syncthreads();

        // coalesced copy of staged keys to g_cand
        const int cnt = min(sh_cnt, STAGE);
        const int base = sh_base;
        for (int i = t; i < cnt; i += TPB) {
            const int p = base + i;
            if (p < CAP) g_cand[b * CAP + p] = stage[i];
        }
    }

    // ============== DONE-COUNTER: last block per image selects ==============
    __threadfence();
    __syncthreads();
    if (t == 0) {
        const int old = atomicAdd(&g_done[b], 1);
        sh_flag = (old == BX - 1);
    }
    __syncthreads();
    if (!sh_flag) return;
    __threadfence();

    unsigned int* hist  = (unsigned int*)buf;            // 8 KB
    unsigned int* start = (unsigned int*)(buf + 8192);   // 8 KB

    int M = g_count[b];

    // ============ FALLBACK (never taken for valid fast path) ============
    if (M < TOPK_ || M > CAP) {
        for (int i = t; i < NB2; i += TPB) hist[i] = 0u;
        if (t == 0) { sh_T = 0; sh_c2 = 0; }
        __syncthreads();

        const float4* sc = (const float4*)(preds + (size_t)b * 3 * HW_);
        for (int i = t; i < HW_ / 4; i += TPB) {
            const float4 w = sc[i];
            atomicAdd(&hist[ordf(w.x) >> 21], 1u);
            atomicAdd(&hist[ordf(w.y) >> 21], 1u);
            atomicAdd(&hist[ordf(w.z) >> 21], 1u);
            atomicAdd(&hist[ordf(w.w) >> 21], 1u);
        }
        __syncthreads();

        unsigned int seg = 0;
        for (int j = 7; j >= 0; j--) seg += hist[t * 8 + j];
        sh_part[t] = seg;
        __syncthreads();
        for (int off = 1; off < TPB; off <<= 1) {
            unsigned int vv = (t + off < TPB) ? sh_part[t + off] : 0u;
            __syncthreads();
            sh_part[t] += vv;
            __syncthreads();
        }
        unsigned int acc = sh_part[t] - seg;
        for (int j = 7; j >= 0; j--) {
            acc += hist[t * 8 + j];
            if (acc >= (unsigned)TOPK_) { atomicMax(&sh_T, t * 8 + j); break; }
        }
        __syncthreads();
        const unsigned int T = (unsigned int)sh_T;

        for (int i = t; i < HW_ / 4; i += TPB) {
            const float4 w = sc[i];
            const float f[4] = {w.x, w.y, w.z, w.w};
#pragma unroll
            for (int k = 0; k < 4; k++) {
                const unsigned int o = ordf(f[k]);
                if ((o >> 21) >= T) {
                    const int p = atomicAdd(&sh_c2, 1);
                    if (p < CAP) {
                        const unsigned int idx = (unsigned int)(i * 4 + k);
                        g_cand[b * CAP + p] = ((ull)o << 32) | (ull)(0xFFFFFFFFu - idx);
                    }
                }
            }
        }
        __syncthreads();
        M = min(sh_c2, CAP);
    }
    M = min(M, CAP);

    // ================= COUNTING SORT (descending) =================
    unsigned int lmin = 0xFFFFFFFFu, lmax = 0u;
    for (int i = t; i < M; i += TPB) {
        const unsigned int h = (unsigned int)(g_cand[b * CAP + i] >> 32);
        lmin = min(lmin, h);
        lmax = max(lmax, h);
    }
#pragma unroll
    for (int off = 16; off > 0; off >>= 1) {
        lmin = min(lmin, __shfl_down_sync(0xFFFFFFFFu, lmin, off));
        lmax = max(lmax, __shfl_down_sync(0xFFFFFFFFu, lmax, off));
    }
    if (lane == 0) { sh_rmin[t >> 5] = lmin; sh_rmax[t >> 5] = lmax; }
    for (int i = t; i < NB2; i += TPB) hist[i] = 0u;
    __syncthreads();
    if (t == 0) {
        unsigned int mn = 0xFFFFFFFFu, mx = 0u;
#pragma unroll
        for (int i = 0; i < 8; i++) { mn = min(mn, sh_rmin[i]); mx = max(mx, sh_rmax[i]); }
        const unsigned int range = mx - mn;
        const int bits = 32 - __clz(range | 1u);
        sh_sh = (bits > 11) ? (unsigned)(bits - 11) : 0u;
        sh_mn = mn;
    }
    __syncthreads();
    const unsigned int mn = sh_mn, shf = sh_sh;

    for (int i = t; i < M; i += TPB) {
        const unsigned int h = (unsigned int)(g_cand[b * CAP + i] >> 32);
        atomicAdd(&hist[(h - mn) >> shf], 1u);
    }
    __syncthreads();

    // suffix scan: start[bk] = #elements in strictly higher buckets
    unsigned int seg = 0;
    for (int j = 7; j >= 0; j--) seg += hist[t * 8 + j];
    sh_part[t] = seg;
    __syncthreads();
    for (int off = 1; off < TPB; off <<= 1) {
        unsigned int vv = (t + off < TPB) ? sh_part[t + off] : 0u;
        __syncthreads();
        sh_part[t] += vv;
        __syncthreads();
    }
    unsigned int run = sh_part[t] - seg;
    for (int j = 7; j >= 0; j--) {
        start[t * 8 + j] = run;
        run += hist[t * 8 + j];
    }
    __syncthreads();

    for (int i = t; i < NB2; i += TPB) hist[i] = 0u;   // -> intra-bucket counters
    __syncthreads();

    for (int i = t; i < M; i += TPB) {
        const ull key = g_cand[b * CAP + i];
        const unsigned int bk = ((unsigned int)(key >> 32) - mn) >> shf;
        const unsigned int p = start[bk] + atomicAdd(&hist[bk], 1u);
        g_sorted[b * CAP + p] = key;
    }
    __syncthreads();

    // per-bucket insertion sort (descending) for buckets intersecting [0, TOPK)
    for (int bk = t; bk < NB2; bk += TPB) {
        const unsigned int c = hist[bk];
        if (c > 1u && start[bk] < (unsigned)TOPK_) {
            ull* s2 = &g_sorted[b * CAP + start[bk]];
            for (unsigned int a = 1; a < c; a++) {
                const ull kv = s2[a];
                int p2 = (int)a - 1;
                while (p2 >= 0 && s2[p2] < kv) { s2[p2 + 1] = s2[p2]; p2--; }
                s2[p2 + 1] = kv;
            }
        }
    }
    __syncthreads();

    // ================= EMIT =================
    const float* ph = preds + (size_t)b * 3 * HW_ + HW_;
    const float* pw = ph + HW_;
    float* boxes  = out;                              // [B, K, 4]
    float* scores = out + (size_t)B_ * TOPK_ * 4;     // [B, K]
    float* keep   = scores + (size_t)B_ * TOPK_;      // [B, K]

    for (int p = t; p < TOPK_; p += TPB) {
        const ull kk = g_sorted[b * CAP + p];
        const unsigned int o = (unsigned int)(kk >> 32);
        const unsigned int u = (o & 0x80000000u) ? (o ^ 0x80000000u) : ~o;
        const float score = __uint_as_float(u);
        const unsigned int idx = 0xFFFFFFFFu - (unsigned int)(kk & 0xFFFFFFFFull);

        const float h = fmaxf(ph[idx], 1e-6f) * (float)H_;
        const float w = fmaxf(pw[idx], 1e-6f) * (float)W_;
        const float cx = (float)(idx % W_);
        const float cy = (float)(idx / W_);

        float* bx = boxes + ((size_t)b * TOPK_ + p) * 4;
        bx[0] = cx - 0.5f * w;
        bx[1] = cy - 0.5f * h;
        bx[2] = cx + 0.5f * w;
        bx[3] = cy + 0.5f * h;
        scores[b * TOPK_ + p] = score;
        keep[b * TOPK_ + p]   = 1.0f;
    }

    if (t == 0) { g_count[b] = 0; g_done[b] = 0; }
}

// ---------------------------------------------------------------------------
extern "C" void kernel_launch(void* const* d_in, const int* in_sizes, int n_in,
                              void* d_out, int out_size) {
    const float* preds = (const float*)d_in[0];
    float* out = (float*)d_out;

    dim3 g(BX, B_);
    k_fused<<<g, TPB>>>(preds, out);
}